// round 13
// baseline (speedup 1.0000x reference)
#include <cuda_runtime.h>
#include <math.h>

typedef unsigned long long ull;

// ---------------- problem constants ----------------
#define Bb   4
#define Cc   64
#define Hh   5
#define Ww   5
#define Kk   3
#define Ee   12
#define NHh  4
#define DHh  3
#define FFf  24
#define HOo  3
#define WOo  3
#define Ll   9
#define Ss   (Bb*Cc*Kk*Kk)       // 2304
#define ROWS (Ss*Ll)             // 20736
#define NC   (Ll*NHh)            // 36
#define YSZ  (Bb*Cc*Hh*Ww)       // 6400

#define DEG  14                  // Taylor degree: pairs j=0..14, moments M_0..M_15

// ---------------- packed f32x2 helpers ----------------
__device__ __forceinline__ ull ffma2(ull a, ull b, ull c) {
    ull d; asm("fma.rn.f32x2 %0, %1, %2, %3;" : "=l"(d) : "l"(a), "l"(b), "l"(c)); return d;
}
__device__ __forceinline__ ull pack2(float lo, float hi) {
    ull d; asm("mov.b64 %0, {%1, %2};" : "=l"(d) : "f"(lo), "f"(hi)); return d;
}
__device__ __forceinline__ void unpack2(ull v, float& lo, float& hi) {
    asm("mov.b64 {%0, %1}, %2;" : "=f"(lo), "=f"(hi) : "l"(v));
}
__device__ __forceinline__ float ex2(float x) {
    float r; asm("ex2.approx.f32 %0, %1;" : "=f"(r) : "f"(x)); return r;
}

// ---------------- fused kernel: moments + tables + Taylor attention + post + fold ----------------
// grid (9 l, 72 s-chunks), 128 threads. Quad lanes = 4 heads of one row:
//   h = tid & 3, s = blockIdx.y*32 + (tid >> 2)
__global__ void k_fused(const float* __restrict__ x,
                        const float* __restrict__ ce,
                        const float* __restrict__ pe,
                        const float* __restrict__ ipw,
                        const float* __restrict__ ipb,
                        const float* __restrict__ wo, const float* __restrict__ bo,
                        const float* __restrict__ g1, const float* __restrict__ b1,
                        const float* __restrict__ f1w, const float* __restrict__ f1b,
                        const float* __restrict__ f2w, const float* __restrict__ f2b,
                        const float* __restrict__ g2, const float* __restrict__ b2,
                        const float* __restrict__ lw, const float* __restrict__ lb,
                        float* __restrict__ y)
{
    __shared__ ulonglong2 sTM[Cc*8];        // per c': 15 pairs {M_j/j!, M_{j+1}/j!} + pad (shared by all h)
    __shared__ float4 sTA[Cc*4];            // (c*4+h): {a0,a1,a2, gamma}
    __shared__ float4 sTB[Cc*4*2];          // (c*4+h)*2 + {0: b*log2e, 1: v0}
    __shared__ float  sUW[4][8];            // per h: {u0,u1,u2, delta, wv0,wv1,wv2, -}
    // post weights
    __shared__ float swo[Ee*Ee], sbo[Ee], sg1[Ee], sb1[Ee];
    __shared__ float s1[FFf*Ee], s1b[FFf], s2[Ee*FFf], s2b[Ee];
    __shared__ float sg2[Ee], sb2[Ee], slw[Ee], slb;

    int l = blockIdx.x;
    int tid = threadIdx.x;
    int oi = l/WOo, oj = l%WOo;
    const unsigned FULL = 0xFFFFFFFFu;

    // ---- post-weight preload ----
    for (int i = tid; i < Ee*Ee; i += 128) swo[i] = wo[i];
    for (int i = tid; i < FFf*Ee; i += 128) { s1[i] = f1w[i]; s2[i] = f2w[i]; }
    if (tid < FFf) s1b[tid] = f1b[tid];
    if (tid < Ee) {
        sbo[tid] = bo[tid];  sg1[tid] = g1[tid];  sb1[tid] = b1[tid];
        s2b[tid] = f2b[tid]; sg2[tid] = g2[tid];  sb2[tid] = b2[tid];
        slw[tid] = lw[tid];
    }
    if (tid == 0) slb = lb[0];

    // ---- moments: 2 threads per channel, 18 samples each (fp32) ----
    {
        int ch = tid >> 1, hf = tid & 1;
        float m[16];
        #pragma unroll
        for (int k = 0; k < 16; k++) m[k] = 0.f;

        #pragma unroll
        for (int bb = 0; bb < 2; bb++) {
            int b = hf*2 + bb;
            #pragma unroll
            for (int p = 0; p < 9; p++) {
                float xv = x[((b*Cc + ch)*Hh + (p/3) + oi)*Ww + (p%3) + oj];
                float pw = 1.f;
                #pragma unroll
                for (int k = 0; k < 16; k++) { m[k] += pw; pw *= xv; }
            }
        }
        #pragma unroll
        for (int k = 0; k < 16; k++) m[k] += __shfl_xor_sync(FULL, m[k], 1);

        if (hf == 0) {
            float* dst = (float*)&sTM[ch*8];
            float invf = 1.f;
            #pragma unroll
            for (int j = 0; j <= DEG; j++) {
                if (j > 0) invf /= (float)j;      // 1/j!
                dst[2*j]   = m[j]   * invf;
                dst[2*j+1] = m[j+1] * invf;
            }
            dst[30] = 0.f; dst[31] = 0.f;
        }
    }

    // ---- tables: thread tid handles channel c = tid&63 for heads {2*hp, 2*hp+1} ----
    const float IS3 = 0.57735026918962576f;
    const float L2E = 1.4426950408889634f;
    {
        int c  = tid & 63;
        int hp = tid >> 6;
        float rc[Ee];
        #pragma unroll
        for (int f = 0; f < Ee; f++) rc[f] = ce[c*Ee + f] + pe[l*Ee + f];

        #pragma unroll
        for (int hh = 0; hh < 2; hh++) {
            int h = hp*2 + hh;
            float a[3], b[3], v0[3], w[3];
            #pragma unroll
            for (int d = 0; d < 3; d++) {
                const float* Wq = ipw + (3*h + d)*Ee;
                const float* Wk = ipw + (Ee + 3*h + d)*Ee;
                const float* Wv = ipw + (2*Ee + 3*h + d)*Ee;
                float aq = ipb[3*h + d];
                float ak = ipb[Ee + 3*h + d];
                float av = ipb[2*Ee + 3*h + d];
                float uk = 0.f;
                #pragma unroll
                for (int f = 0; f < Ee; f++) {
                    aq += Wq[f]*rc[f]; ak += Wk[f]*rc[f]; av += Wv[f]*rc[f];
                    uk += Wk[f];
                }
                a[d] = aq*IS3; b[d] = ak; v0[d] = av; w[d] = uk;
            }
            float gamma = a[0]*w[0] + a[1]*w[1] + a[2]*w[2];
            sTA[c*4 + h] = make_float4(a[0], a[1], a[2], gamma);
            sTB[(c*4 + h)*2 + 0] = make_float4(b[0]*L2E, b[1]*L2E, b[2]*L2E, 0.f);
            sTB[(c*4 + h)*2 + 1] = make_float4(v0[0], v0[1], v0[2], 0.f);
        }
    }
    if (tid >= 124) {
        int h = tid - 124;
        float u[3], w[3], wv[3];
        #pragma unroll
        for (int d = 0; d < 3; d++) {
            float uq = 0.f, uk = 0.f, uv = 0.f;
            #pragma unroll
            for (int f = 0; f < Ee; f++) {
                uq += ipw[(3*h + d)*Ee + f];
                uk += ipw[(Ee + 3*h + d)*Ee + f];
                uv += ipw[(2*Ee + 3*h + d)*Ee + f];
            }
            u[d] = uq*IS3; w[d] = uk; wv[d] = uv;
        }
        sUW[h][0] = u[0]; sUW[h][1] = u[1]; sUW[h][2] = u[2];
        sUW[h][3] = u[0]*w[0] + u[1]*w[1] + u[2]*w[2];   // delta
        sUW[h][4] = wv[0]; sUW[h][5] = wv[1]; sUW[h][6] = wv[2];
    }
    __syncthreads();

    // ---- main attention loop: lane = head h of row (l, s) ----
    int h = tid & 3;
    int s = blockIdx.y*32 + (tid >> 2);
    int bi = s / (Cc*9);
    int rem = s % (Cc*9);
    int c = rem / 9, p = rem % 9;
    int pi = p/3, pj = p%3;
    float xv = x[((bi*Cc + c)*Hh + pi + oi)*Ww + pj + oj];

    float4 ag = sTA[c*4 + h];
    float u0 = sUW[h][0], u1 = sUW[h][1], u2 = sUW[h][2], delta = sUW[h][3];
    float wv0 = sUW[h][4], wv1 = sUW[h][5], wv2 = sUW[h][6];

    float q0 = ag.x + xv*u0;
    float q1 = ag.y + xv*u1;
    float q2 = ag.z + xv*u2;
    float g  = ag.w + xv*delta;             // q~·w (natural scale)
    ull  gpk = pack2(g, g);

    float den = 0.f, o0 = 0.f, o1 = 0.f, o2 = 0.f;

    #pragma unroll 2
    for (int cp = 0; cp < Cc; cp++) {
        float4 bb = sTB[(cp*4 + h)*2];
        float4 vv = sTB[(cp*4 + h)*2 + 1];
        const ull* Cp = (const ull*)&sTM[cp*8];

        float earg = fmaf(q0, bb.x, fmaf(q1, bb.y, q2*bb.z));   // pre-scaled *log2e
        float E = ex2(earg);

        ull acc = Cp[DEG];
        #pragma unroll
        for (int j = DEG-1; j >= 0; j--) acc = ffma2(acc, gpk, Cp[j]);
        float S0, S1; unpack2(acc, S0, S1);

        float ES0 = E*S0, ES1 = E*S1;
        den += ES0;
        o0 = fmaf(ES1, wv0, fmaf(ES0, vv.x, o0));
        o1 = fmaf(ES1, wv1, fmaf(ES0, vv.y, o1));
        o2 = fmaf(ES1, wv2, fmaf(ES0, vv.z, o2));
    }

    float inv = 1.f / den;
    float on0 = o0*inv, on1 = o1*inv, on2 = o2*inv;

    // ---- quad gather: assemble full cx[12] in every lane ----
    int lane = tid & 31;
    int qbase = lane & ~3;
    float cx[Ee];
    #pragma unroll
    for (int hh = 0; hh < 4; hh++) {
        int src = qbase | hh;
        cx[hh*3+0] = __shfl_sync(FULL, on0, src);
        cx[hh*3+1] = __shfl_sync(FULL, on1, src);
        cx[hh*3+2] = __shfl_sync(FULL, on2, src);
    }

    // ---- post (quad-split, ebase = h*3) ----
    int ebase = h*3;

    float t[3];
    #pragma unroll
    for (int eo = 0; eo < 3; eo++) {
        int e = ebase + eo;
        float acc = sbo[e];
        #pragma unroll
        for (int f = 0; f < Ee; f++) acc += cx[f] * swo[e*Ee + f];
        t[eo] = (__ldg(&ce[c*Ee + e]) + __ldg(&pe[l*Ee + e]) + xv) + acc;
    }

    float sl = t[0] + t[1] + t[2];
    sl += __shfl_xor_sync(FULL, sl, 1);
    sl += __shfl_xor_sync(FULL, sl, 2);
    float mu = sl * (1.f/Ee);
    float vl = 0.f;
    #pragma unroll
    for (int eo = 0; eo < 3; eo++) { float d = t[eo]-mu; vl += d*d; }
    vl += __shfl_xor_sync(FULL, vl, 1);
    vl += __shfl_xor_sync(FULL, vl, 2);
    float rs = rsqrtf(vl*(1.f/Ee) + 1e-5f);

    float h1[3];
    #pragma unroll
    for (int eo = 0; eo < 3; eo++) {
        int e = ebase + eo;
        h1[eo] = (t[eo]-mu)*rs*sg1[e] + sb1[e];
    }

    float hid[FFf];
    #pragma unroll
    for (int f = 0; f < FFf; f++) {
        float pd = h1[0]*s1[f*Ee + ebase] + h1[1]*s1[f*Ee + ebase + 1] + h1[2]*s1[f*Ee + ebase + 2];
        pd += __shfl_xor_sync(FULL, pd, 1);
        pd += __shfl_xor_sync(FULL, pd, 2);
        hid[f] = fmaxf(pd + s1b[f], 0.f);
    }

    float t2[3];
    #pragma unroll
    for (int eo = 0; eo < 3; eo++) {
        int e = ebase + eo;
        float acc = s2b[e];
        #pragma unroll
        for (int f = 0; f < FFf; f++) acc += hid[f] * s2[e*FFf + f];
        t2[eo] = h1[eo] + acc;
    }

    float sl2 = t2[0] + t2[1] + t2[2];
    sl2 += __shfl_xor_sync(FULL, sl2, 1);
    sl2 += __shfl_xor_sync(FULL, sl2, 2);
    float mu2 = sl2 * (1.f/Ee);
    float vl2 = 0.f;
    #pragma unroll
    for (int eo = 0; eo < 3; eo++) { float d = t2[eo]-mu2; vl2 += d*d; }
    vl2 += __shfl_xor_sync(FULL, vl2, 1);
    vl2 += __shfl_xor_sync(FULL, vl2, 2);
    float rs2 = rsqrtf(vl2*(1.f/Ee) + 1e-5f);

    float pl = 0.f;
    #pragma unroll
    for (int eo = 0; eo < 3; eo++) {
        int e = ebase + eo;
        pl += ((t2[eo]-mu2)*rs2*sg2[e] + sb2[e]) * slw[e];
    }
    pl += __shfl_xor_sync(FULL, pl, 1);
    pl += __shfl_xor_sync(FULL, pl, 2);

    if (h == 0) {
        float proj = slb + pl;
        atomicAdd(&y[((bi*Cc + c)*Hh + (pi+oi))*Ww + (pj+oj)], proj);
    }
}

// ---------------- launch ----------------
extern "C" void kernel_launch(void* const* d_in, const int* in_sizes, int n_in,
                              void* d_out, int out_size)
{
    const float* x    = (const float*)d_in[0];
    const float* ce   = (const float*)d_in[1];
    const float* pe   = (const float*)d_in[2];
    const float* ipw  = (const float*)d_in[3];
    const float* ipb  = (const float*)d_in[4];
    const float* opw  = (const float*)d_in[5];
    const float* opb  = (const float*)d_in[6];
    const float* ln1w = (const float*)d_in[7];
    const float* ln1b = (const float*)d_in[8];
    const float* f1w  = (const float*)d_in[9];
    const float* f1b  = (const float*)d_in[10];
    const float* f2w  = (const float*)d_in[11];
    const float* f2b  = (const float*)d_in[12];
    const float* ln2w = (const float*)d_in[13];
    const float* ln2b = (const float*)d_in[14];
    const float* lw   = (const float*)d_in[15];
    const float* lb   = (const float*)d_in[16];
    float* y = (float*)d_out;

    cudaMemsetAsync(y, 0, YSZ*sizeof(float));
    dim3 grid(Ll, Ss/32);
    k_fused<<<grid, 128>>>(x, ce, pe, ipw, ipb, opw, opb, ln1w, ln1b,
                           f1w, f1b, f2w, f2b, ln2w, ln2b, lw, lb, y);
}

// round 14
// speedup vs baseline: 1.2066x; 1.2066x over previous
#include <cuda_runtime.h>
#include <math.h>

typedef unsigned long long ull;

// ---------------- problem constants ----------------
#define Bb   4
#define Cc   64
#define Hh   5
#define Ww   5
#define Kk   3
#define Ee   12
#define NHh  4
#define DHh  3
#define FFf  24
#define HOo  3
#define WOo  3
#define Ll   9
#define Ss   (Bb*Cc*Kk*Kk)       // 2304
#define ROWS (Ss*Ll)             // 20736
#define NC   (Ll*NHh)            // 36
#define YSZ  (Bb*Cc*Hh*Ww)       // 6400

#define DEG  14                  // Taylor degree: pairs j=0..14, moments M_0..M_15
#define QPB  64                  // threads per attention block (2 warps)

// ---------------- scratch ----------------
__device__ float4 g_ctx[NC*Ss];         // attention output per (combo, s)

// ---------------- packed f32x2 helpers ----------------
__device__ __forceinline__ ull ffma2(ull a, ull b, ull c) {
    ull d; asm("fma.rn.f32x2 %0, %1, %2, %3;" : "=l"(d) : "l"(a), "l"(b), "l"(c)); return d;
}
__device__ __forceinline__ ull pack2(float lo, float hi) {
    ull d; asm("mov.b64 %0, {%1, %2};" : "=l"(d) : "f"(lo), "f"(hi)); return d;
}
__device__ __forceinline__ void unpack2(ull v, float& lo, float& hi) {
    asm("mov.b64 {%0, %1}, %2;" : "=f"(lo), "=f"(hi) : "l"(v));
}
__device__ __forceinline__ float ex2(float x) {
    float r; asm("ex2.approx.f32 %0, %1;" : "=f"(r) : "f"(x)); return r;
}

// ---------------- kernel 1: attention (moments + tables + Taylor softmax) ----------------
// grid (36 combos, 18 q-chunks), 64 threads, TWO queries per thread (sA, sA+64).
__global__ void k_attn(const float* __restrict__ x,
                       const float* __restrict__ ce,
                       const float* __restrict__ pe,
                       const float* __restrict__ ipw,
                       const float* __restrict__ ipb,
                       float* __restrict__ y)
{
    __shared__ ulonglong2 sTM[Cc*8];        // per c': 15 pairs {M_j/j!, M_{j+1}/j!} + pad
    __shared__ float4 sTB[Cc*2];            // per c': {b*log2e, 0}, {v0, 0}
    __shared__ float4 sTA[Cc];              // per c: {a0,a1,a2, gamma}
    __shared__ float  sUW[8];               // {u0,u1,u2, delta, wv0,wv1,wv2, -}

    int combo = blockIdx.x;
    int l = combo >> 2, h = combo & 3;
    int tid = threadIdx.x;
    int oi = l/WOo, oj = l%WOo;

    // zero output once (combo 0 blocks; separate launch precedes k_post atomics)
    if (combo == 0) {
        for (int i = blockIdx.y*QPB + tid; i < YSZ; i += 18*QPB) y[i] = 0.f;
    }

    // ---- moments: one thread per channel, 36 samples (fp32) ----
    {
        int ch = tid;
        float m[16];
        #pragma unroll
        for (int k = 0; k < 16; k++) m[k] = 0.f;

        #pragma unroll
        for (int b = 0; b < Bb; b++) {
            #pragma unroll
            for (int p = 0; p < 9; p++) {
                float xv = x[((b*Cc + ch)*Hh + (p/3) + oi)*Ww + (p%3) + oj];
                float pw = 1.f;
                #pragma unroll
                for (int k = 0; k < 16; k++) { m[k] += pw; pw *= xv; }
            }
        }
        float* dst = (float*)&sTM[ch*8];
        float invf = 1.f;
        #pragma unroll
        for (int j = 0; j <= DEG; j++) {
            if (j > 0) invf /= (float)j;      // 1/j!
            dst[2*j]   = m[j]   * invf;
            dst[2*j+1] = m[j+1] * invf;
        }
        dst[30] = 0.f; dst[31] = 0.f;
    }

    // ---- tables: one thread per channel, this block's head only ----
    const float IS3 = 0.57735026918962576f;   // 1/sqrt(3)
    const float L2E = 1.4426950408889634f;
    {
        int c = tid;
        float rc[Ee];
        #pragma unroll
        for (int f = 0; f < Ee; f++) rc[f] = ce[c*Ee + f] + pe[l*Ee + f];

        float a[3], b[3], v0[3], w[3];
        #pragma unroll
        for (int d = 0; d < 3; d++) {
            const float* Wq = ipw + (3*h + d)*Ee;
            const float* Wk = ipw + (Ee + 3*h + d)*Ee;
            const float* Wv = ipw + (2*Ee + 3*h + d)*Ee;
            float aq = ipb[3*h + d];
            float ak = ipb[Ee + 3*h + d];
            float av = ipb[2*Ee + 3*h + d];
            float uk = 0.f;
            #pragma unroll
            for (int f = 0; f < Ee; f++) {
                aq += Wq[f]*rc[f]; ak += Wk[f]*rc[f]; av += Wv[f]*rc[f];
                uk += Wk[f];
            }
            a[d] = aq*IS3; b[d] = ak; v0[d] = av; w[d] = uk;
        }
        float gamma = a[0]*w[0] + a[1]*w[1] + a[2]*w[2];
        sTA[c] = make_float4(a[0], a[1], a[2], gamma);
        sTB[c*2 + 0] = make_float4(b[0]*L2E, b[1]*L2E, b[2]*L2E, 0.f);
        sTB[c*2 + 1] = make_float4(v0[0], v0[1], v0[2], 0.f);
    }
    if (tid == 0) {
        float u[3], w[3], wv[3];
        #pragma unroll
        for (int d = 0; d < 3; d++) {
            float uq = 0.f, uk = 0.f, uv = 0.f;
            #pragma unroll
            for (int f = 0; f < Ee; f++) {
                uq += ipw[(3*h + d)*Ee + f];
                uk += ipw[(Ee + 3*h + d)*Ee + f];
                uv += ipw[(2*Ee + 3*h + d)*Ee + f];
            }
            u[d] = uq*IS3; w[d] = uk; wv[d] = uv;
        }
        sUW[0] = u[0]; sUW[1] = u[1]; sUW[2] = u[2];
        sUW[3] = u[0]*w[0] + u[1]*w[1] + u[2]*w[2];   // delta
        sUW[4] = wv[0]; sUW[5] = wv[1]; sUW[6] = wv[2];
    }
    __syncthreads();

    // ---- main loop: 2 queries per thread ----
    int sA = blockIdx.y*(2*QPB) + tid;
    int sB = sA + QPB;

    int biA = sA / (Cc*9), remA = sA % (Cc*9);
    int cA = remA / 9, pA = remA % 9;
    float xvA = x[((biA*Cc + cA)*Hh + (pA/3) + oi)*Ww + (pA%3) + oj];

    int biB = sB / (Cc*9), remB = sB % (Cc*9);
    int cB = remB / 9, pB = remB % 9;
    float xvB = x[((biB*Cc + cB)*Hh + (pB/3) + oi)*Ww + (pB%3) + oj];

    float u0 = sUW[0], u1 = sUW[1], u2 = sUW[2], delta = sUW[3];
    float wv0 = sUW[4], wv1 = sUW[5], wv2 = sUW[6];

    float4 agA = sTA[cA];
    float qA0 = agA.x + xvA*u0, qA1 = agA.y + xvA*u1, qA2 = agA.z + xvA*u2;
    float gA  = agA.w + xvA*delta;
    ull  gpkA = pack2(gA, gA);

    float4 agB = sTA[cB];
    float qB0 = agB.x + xvB*u0, qB1 = agB.y + xvB*u1, qB2 = agB.z + xvB*u2;
    float gB  = agB.w + xvB*delta;
    ull  gpkB = pack2(gB, gB);

    float denA = 0.f, oA0 = 0.f, oA1 = 0.f, oA2 = 0.f;
    float denB = 0.f, oB0 = 0.f, oB1 = 0.f, oB2 = 0.f;

    #pragma unroll 2
    for (int cp = 0; cp < Cc; cp++) {
        float4 bb = sTB[cp*2];
        float4 vv = sTB[cp*2 + 1];
        const ull* Cp = (const ull*)&sTM[cp*8];

        float eargA = fmaf(qA0, bb.x, fmaf(qA1, bb.y, qA2*bb.z));   // pre-scaled *log2e
        float eargB = fmaf(qB0, bb.x, fmaf(qB1, bb.y, qB2*bb.z));
        float EA = ex2(eargA);
        float EB = ex2(eargB);

        ull accA = Cp[DEG];
        ull accB = Cp[DEG];
        #pragma unroll
        for (int j = DEG-1; j >= 0; j--) {
            accA = ffma2(accA, gpkA, Cp[j]);
            accB = ffma2(accB, gpkB, Cp[j]);
        }
        float S0A, S1A; unpack2(accA, S0A, S1A);
        float S0B, S1B; unpack2(accB, S0B, S1B);

        float ESA0 = EA*S0A, ESA1 = EA*S1A;
        denA += ESA0;
        oA0 = fmaf(ESA1, wv0, fmaf(ESA0, vv.x, oA0));
        oA1 = fmaf(ESA1, wv1, fmaf(ESA0, vv.y, oA1));
        oA2 = fmaf(ESA1, wv2, fmaf(ESA0, vv.z, oA2));

        float ESB0 = EB*S0B, ESB1 = EB*S1B;
        denB += ESB0;
        oB0 = fmaf(ESB1, wv0, fmaf(ESB0, vv.x, oB0));
        oB1 = fmaf(ESB1, wv1, fmaf(ESB0, vv.y, oB1));
        oB2 = fmaf(ESB1, wv2, fmaf(ESB0, vv.z, oB2));
    }

    float invA = 1.f / denA;
    float invB = 1.f / denB;
    g_ctx[combo*Ss + sA] = make_float4(oA0*invA, oA1*invA, oA2*invA, 0.f);
    g_ctx[combo*Ss + sB] = make_float4(oB0*invB, oB1*invB, oB2*invB, 0.f);
}

// ---------------- kernel 2: out_proj + LN1 + FFN + LN2 + linear + fold ----------------
// FOUR threads per row; global loads hoisted above the weight preload.
__global__ void k_post(const float* __restrict__ x,
                       const float* __restrict__ cemb, const float* __restrict__ pemb,
                       const float* __restrict__ wo, const float* __restrict__ bo,
                       const float* __restrict__ g1, const float* __restrict__ b1,
                       const float* __restrict__ f1w, const float* __restrict__ f1b,
                       const float* __restrict__ f2w, const float* __restrict__ f2b,
                       const float* __restrict__ g2, const float* __restrict__ b2,
                       const float* __restrict__ lw, const float* __restrict__ lb,
                       float* __restrict__ y)
{
    __shared__ float swo[Ee*Ee], sbo[Ee], sg1[Ee], sb1[Ee];
    __shared__ float s1[FFf*Ee], s1b[FFf], s2[Ee*FFf], s2b[Ee];
    __shared__ float sg2[Ee], sb2[Ee], slw[Ee], slb;

    int gt = blockIdx.x*blockDim.x + threadIdx.x;
    int row = gt >> 2;                  // l-major: row = l*Ss + s
    int q   = gt & 3;                   // quad lane
    int l = row / Ss, s = row % Ss;
    const unsigned FULL = 0xFFFFFFFFu;

    // ---- hoisted global loads (overlap with preload + barrier) ----
    float cx[Ee];
    #pragma unroll
    for (int h = 0; h < NHh; h++) {
        float4 o = g_ctx[(l*NHh + h)*Ss + s];
        cx[h*3] = o.x; cx[h*3+1] = o.y; cx[h*3+2] = o.z;
    }
    int bi = s / (Cc*9);
    int rem = s % (Cc*9);
    int c = rem / 9, p = rem % 9;
    int pi = p/3, pj = p%3;
    int oi = l/WOo, oj = l%WOo;
    float xv = x[((bi*Cc + c)*Hh + pi + oi)*Ww + pj + oj];

    int ebase = q*3;
    float res[3];
    #pragma unroll
    for (int eo = 0; eo < 3; eo++) {
        int e = ebase + eo;
        res[eo] = __ldg(&cemb[c*Ee + e]) + __ldg(&pemb[l*Ee + e]) + xv;
    }

    // ---- weight preload ----
    for (int i = threadIdx.x; i < Ee*Ee; i += blockDim.x) swo[i] = wo[i];
    for (int i = threadIdx.x; i < FFf*Ee; i += blockDim.x) { s1[i] = f1w[i]; s2[i] = f2w[i]; }
    if (threadIdx.x < FFf) s1b[threadIdx.x] = f1b[threadIdx.x];
    if (threadIdx.x < Ee) {
        sbo[threadIdx.x] = bo[threadIdx.x];
        sg1[threadIdx.x] = g1[threadIdx.x];
        sb1[threadIdx.x] = b1[threadIdx.x];
        s2b[threadIdx.x] = f2b[threadIdx.x];
        sg2[threadIdx.x] = g2[threadIdx.x];
        sb2[threadIdx.x] = b2[threadIdx.x];
        slw[threadIdx.x] = lw[threadIdx.x];
    }
    if (threadIdx.x == 0) slb = lb[0];
    __syncthreads();

    // ---- out_proj + residual (own 3 outputs) ----
    float t[3];
    #pragma unroll
    for (int eo = 0; eo < 3; eo++) {
        int e = ebase + eo;
        float acc = sbo[e];
        #pragma unroll
        for (int f = 0; f < Ee; f++) acc += cx[f] * swo[e*Ee + f];
        t[eo] = res[eo] + acc;
    }

    // ---- LN1 (quad reduction) ----
    float sl = t[0] + t[1] + t[2];
    sl += __shfl_xor_sync(FULL, sl, 1);
    sl += __shfl_xor_sync(FULL, sl, 2);
    float mu = sl * (1.f/Ee);
    float vl = 0.f;
    #pragma unroll
    for (int eo = 0; eo < 3; eo++) { float d = t[eo]-mu; vl += d*d; }
    vl += __shfl_xor_sync(FULL, vl, 1);
    vl += __shfl_xor_sync(FULL, vl, 2);
    float rs = rsqrtf(vl*(1.f/Ee) + 1e-5f);

    float h1[3];
    #pragma unroll
    for (int eo = 0; eo < 3; eo++) {
        int e = ebase + eo;
        h1[eo] = (t[eo]-mu)*rs*sg1[e] + sb1[e];
    }

    // ---- FF1: partial-dot own 3 features for all 24 hidden; quad-reduce ----
    float hid[FFf];
    #pragma unroll
    for (int f = 0; f < FFf; f++) {
        float pd = h1[0]*s1[f*Ee + ebase] + h1[1]*s1[f*Ee + ebase + 1] + h1[2]*s1[f*Ee + ebase + 2];
        pd += __shfl_xor_sync(FULL, pd, 1);
        pd += __shfl_xor_sync(FULL, pd, 2);
        hid[f] = fmaxf(pd + s1b[f], 0.f);
    }

    // ---- FF2 + residual (own 3 outputs, full hidden) ----
    float t2[3];
    #pragma unroll
    for (int eo = 0; eo < 3; eo++) {
        int e = ebase + eo;
        float acc = s2b[e];
        #pragma unroll
        for (int f = 0; f < FFf; f++) acc += hid[f] * s2[e*FFf + f];
        t2[eo] = h1[eo] + acc;
    }

    // ---- LN2 (quad reduction) ----
    float sl2 = t2[0] + t2[1] + t2[2];
    sl2 += __shfl_xor_sync(FULL, sl2, 1);
    sl2 += __shfl_xor_sync(FULL, sl2, 2);
    float mu2 = sl2 * (1.f/Ee);
    float vl2 = 0.f;
    #pragma unroll
    for (int eo = 0; eo < 3; eo++) { float d = t2[eo]-mu2; vl2 += d*d; }
    vl2 += __shfl_xor_sync(FULL, vl2, 1);
    vl2 += __shfl_xor_sync(FULL, vl2, 2);
    float rs2 = rsqrtf(vl2*(1.f/Ee) + 1e-5f);

    // ---- final linear (quad-reduced dot) ----
    float pl = 0.f;
    #pragma unroll
    for (int eo = 0; eo < 3; eo++) {
        int e = ebase + eo;
        pl += ((t2[eo]-mu2)*rs2*sg2[e] + sb2[e]) * slw[e];
    }
    pl += __shfl_xor_sync(FULL, pl, 1);
    pl += __shfl_xor_sync(FULL, pl, 2);

    if (q == 0) {
        float proj = slb + pl;
        atomicAdd(&y[((bi*Cc + c)*Hh + (pi+oi))*Ww + (pj+oj)], proj);
    }
}

// ---------------- launch ----------------
extern "C" void kernel_launch(void* const* d_in, const int* in_sizes, int n_in,
                              void* d_out, int out_size)
{
    const float* x    = (const float*)d_in[0];
    const float* ce   = (const float*)d_in[1];
    const float* pe   = (const float*)d_in[2];
    const float* ipw  = (const float*)d_in[3];
    const float* ipb  = (const float*)d_in[4];
    const float* opw  = (const float*)d_in[5];
    const float* opb  = (const float*)d_in[6];
    const float* ln1w = (const float*)d_in[7];
    const float* ln1b = (const float*)d_in[8];
    const float* f1w  = (const float*)d_in[9];
    const float* f1b  = (const float*)d_in[10];
    const float* f2w  = (const float*)d_in[11];
    const float* f2b  = (const float*)d_in[12];
    const float* ln2w = (const float*)d_in[13];
    const float* ln2b = (const float*)d_in[14];
    const float* lw   = (const float*)d_in[15];
    const float* lb   = (const float*)d_in[16];
    float* y = (float*)d_out;

    dim3 agrid(NC, Ss/(2*QPB));
    k_attn<<<agrid, QPB>>>(x, ce, pe, ipw, ipb, y);
    k_post<<<ROWS*4/128, 128>>>(x, ce, pe, opw, opb, ln1w, ln1b,
                                f1w, f1b, f2w, f2b, ln2w, ln2b, lw, lb, y);
}